// round 17
// baseline (speedup 1.0000x reference)
#include <cuda_runtime.h>
#include <cuda_bf16.h>
#include <cstdint>

#define BB 256
#define TT 512
#define DD 128
#define HH 512
#define CC 10

#define M_BLK 64
#define NG_BLK 64            // gate cols per CTA (16 h-cols)
#define NT_M 4
#define NT_N 32
#define GRID_SZ 128
#define NTHR 256             // 8 warps (2/SMSP); warp tile 32m x 16n
#define NCHUNK 10            // K = 640 in chunks of 64

// SMEM layout (bytes)
#define OFF_BIAS 0
#define OFF_GATES 256                    // [64][68] f32
#define GSTRIDE 68
#define OFF_Z 17664                      // 2 buf x (hi,lo) x [64][72] bf16
#define SZB 144                          // Z row stride bytes (72 bf16)
#define Z_VER 9216
#define Z_BUF 18432
#define OFF_W 54528                      // (hi,lo) x [64][648] bf16
#define SWB 1296                         // W row stride bytes (648 bf16)
#define W_VER 82944
#define SMEM_TOTAL 220416

// Persistent device state
__device__ __nv_bfloat16 g_Xhi[(size_t)BB*TT*DD];
__device__ __nv_bfloat16 g_Xlo[(size_t)BB*TT*DD];
__device__ __nv_bfloat16 g_hbf[2][2][BB*HH];      // [ping][hi/lo]
__device__ float g_partial[NT_N][BB][CC];
struct __align__(128) Bar { unsigned count; unsigned gen; unsigned pad[30]; };
__device__ Bar g_mbar[NT_M];
__device__ Bar g_fbar;

__device__ __forceinline__ float fast_tanh(float x) {
    float y; asm("tanh.approx.f32 %0, %1;" : "=f"(y) : "f"(x)); return y;
}
__device__ __forceinline__ float fast_sigmoid(float x) {
    return 0.5f * fast_tanh(0.5f * x) + 0.5f;
}

// m16n8k16 bf16 MMA (base PTX, sm_80+; compiles for compute_103)
__device__ __forceinline__ void mma16816(float* d, const uint32_t* a,
                                         const uint32_t* b) {
    asm volatile(
        "mma.sync.aligned.m16n8k16.row.col.f32.bf16.bf16.f32 "
        "{%0,%1,%2,%3}, {%4,%5,%6,%7}, {%8,%9}, {%0,%1,%2,%3};"
        : "+f"(d[0]), "+f"(d[1]), "+f"(d[2]), "+f"(d[3])
        : "r"(a[0]), "r"(a[1]), "r"(a[2]), "r"(a[3]), "r"(b[0]), "r"(b[1]));
}

__device__ __forceinline__ uint32_t bf2(float a, float b) {
    unsigned short ua = __bfloat16_as_ushort(__float2bfloat16(a));
    unsigned short ub = __bfloat16_as_ushort(__float2bfloat16(b));
    return (uint32_t)ua | ((uint32_t)ub << 16);
}

// ---- init: split X to bf16 hi/lo, zero h ping 0, reset barriers -----------
__global__ void lstm_init(const float* __restrict__ X) {
    size_t stride = (size_t)gridDim.x * blockDim.x;
    size_t i0 = (size_t)blockIdx.x * blockDim.x + threadIdx.x;
    const size_t NX = (size_t)BB * TT * DD;
    for (size_t i = i0; i < NX; i += stride) {
        float x = X[i];
        __nv_bfloat16 hi = __float2bfloat16(x);
        g_Xhi[i] = hi;
        g_Xlo[i] = __float2bfloat16(x - __bfloat162float(hi));
    }
    __nv_bfloat16* hz = &g_hbf[0][0][0];
    for (size_t i = i0; i < (size_t)2 * BB * HH; i += stride)
        hz[i] = __float2bfloat16(0.f);
    if (i0 == 0) {
        for (int m = 0; m < NT_M; m++) { g_mbar[m].count = 0; g_mbar[m].gen = 0; }
        g_fbar.count = 0;
    }
}

// ---- main persistent kernel ------------------------------------------------
__global__ void __launch_bounds__(NTHR, 1)
lstm_mma(const float* __restrict__ W_ih,
         const float* __restrict__ W_hh,
         const float* __restrict__ b_ih,
         const float* __restrict__ b_hh,
         const float* __restrict__ W_lin,
         const float* __restrict__ b_lin,
         float* __restrict__ out)
{
    extern __shared__ char smem[];
    float* bsm   = (float*)(smem + OFF_BIAS);
    float* gates = (float*)(smem + OFF_GATES);

    const int tid   = threadIdx.x;
    const int lane  = tid & 31;
    const int w     = tid >> 5;           // 0..7
    const int g     = lane >> 2;          // fragment group row
    const int tig   = lane & 3;           // thread-in-group
    const int cta   = blockIdx.x;
    const int mtile = cta >> 5;
    const int ntile = cta & 31;
    const int m0    = mtile * M_BLK;
    const int c0    = ntile * 16;
    const int mtb   = (w & 1) * 32;       // warp m offset
    const int ntb   = (w >> 1) * 16;      // warp n offset (0,16,32,48)
    const int sm    = tid & 63;           // staging / epilogue row
    const int sver  = (tid >> 6) & 1;     // staging version (0=hi,1=lo)
    const int skh   = tid >> 7;           // staging k-half (0/1, 64B each)

    // ---- one-time W staging: col n = g*16 + j <-> weight row r = g*H+c0+j
    for (int idx = tid; idx < NG_BLK * (DD + HH); idx += NTHR) {
        int n = idx / (DD + HH);
        int k = idx - n * (DD + HH);
        int gg = n >> 4, j = n & 15;
        int r = gg * HH + c0 + j;
        float wv = (k < DD) ? W_ih[r * DD + k] : W_hh[r * HH + (k - DD)];
        __nv_bfloat16 hi = __float2bfloat16(wv);
        __nv_bfloat16 lo = __float2bfloat16(wv - __bfloat162float(hi));
        *(__nv_bfloat16*)(smem + OFF_W + n * SWB + k * 2) = hi;
        *(__nv_bfloat16*)(smem + OFF_W + W_VER + n * SWB + k * 2) = lo;
    }
    if (tid < NG_BLK) {
        int gg = tid >> 4, j = tid & 15;
        int r = gg * HH + c0 + j;
        bsm[tid] = b_ih[r] + b_hh[r];
    }
    __syncthreads();

    // epilogue: thread owns (row sm, h-cols jb..jb+3)
    const int jb = (tid >> 6) * 4;        // 0,4,8,12
    const float4 bi  = *(const float4*)(bsm + jb);
    const float4 bff = *(const float4*)(bsm + 16 + jb);
    const float4 bgg = *(const float4*)(bsm + 32 + jb);
    const float4 boo = *(const float4*)(bsm + 48 + jb);

    float c_st[4], hsum[4];
#pragma unroll
    for (int j = 0; j < 4; j++) { c_st[j] = 0.f; hsum[j] = 0.f; }

    for (int t = 0; t < TT; t++) {
        const int ping = t & 1;
        float D[2][2][4];
#pragma unroll
        for (int mt = 0; mt < 2; mt++)
#pragma unroll
            for (int nt = 0; nt < 2; nt++)
#pragma unroll
                for (int q = 0; q < 4; q++) D[mt][nt][q] = 0.f;

        // ---- prefetch chunk 0 (X): 64B per thread ----
        uint4 v[4];
        {
            const __nv_bfloat16* xs = sver ? g_Xlo : g_Xhi;
            const uint4* s4 = (const uint4*)
                (xs + ((size_t)(m0 + sm) * TT + t) * DD + skh * 32);
#pragma unroll
            for (int i = 0; i < 4; i++) v[i] = __ldg(s4 + i);
            char* zd = smem + OFF_Z + sver * Z_VER + sm * SZB + skh * 64;
#pragma unroll
            for (int i = 0; i < 4; i++) *(uint4*)(zd + i * 16) = v[i];
        }
        __syncthreads();

#pragma unroll 1
        for (int c = 0; c < NCHUNK; c++) {
            const int buf = c & 1;
            if (c == 1 && t > 0) {       // h(t-1) must be published before chunk 2
                if (tid == 0) {
                    while ((int)(*(volatile unsigned*)&g_mbar[mtile].gen) < t) { }
                    __threadfence();
                }
                __syncthreads();
            }
            if (c < NCHUNK - 1) {        // LDG chunk c+1
                const int cn = c + 1;
                if (cn < 2) {
                    const __nv_bfloat16* xs = sver ? g_Xlo : g_Xhi;
                    const uint4* s4 = (const uint4*)
                        (xs + ((size_t)(m0 + sm) * TT + t) * DD + cn * 64 + skh * 32);
#pragma unroll
                    for (int i = 0; i < 4; i++) v[i] = __ldg(s4 + i);
                } else {
                    const uint4* s4 = (const uint4*)
                        (&g_hbf[ping][sver][(size_t)(m0 + sm) * HH
                                            + (cn * 64 - DD) + skh * 32]);
#pragma unroll
                    for (int i = 0; i < 4; i++) v[i] = __ldcg(s4 + i);
                }
            }

            // ---- MMA on chunk c (4 k-steps of 16) ----
            {
                const char* zb = smem + OFF_Z + buf * Z_BUF + (mtb + g) * SZB + tig * 4;
                const char* wb = smem + OFF_W + (ntb + g) * SWB + c * 128 + tig * 4;
#pragma unroll
                for (int s = 0; s < 4; s++) {
                    uint32_t Ah[2][4], Al[2][4], Bh[2][2], Bl[2][2];
#pragma unroll
                    for (int mt = 0; mt < 2; mt++) {
                        const char* p = zb + s * 32 + mt * 2304;   // 16 rows * 144B
                        Ah[mt][0] = *(const uint32_t*)(p);
                        Ah[mt][1] = *(const uint32_t*)(p + 1152);  // +8 rows
                        Ah[mt][2] = *(const uint32_t*)(p + 16);    // +8 cols
                        Ah[mt][3] = *(const uint32_t*)(p + 1168);
                        Al[mt][0] = *(const uint32_t*)(p + Z_VER);
                        Al[mt][1] = *(const uint32_t*)(p + Z_VER + 1152);
                        Al[mt][2] = *(const uint32_t*)(p + Z_VER + 16);
                        Al[mt][3] = *(const uint32_t*)(p + Z_VER + 1168);
                    }
#pragma unroll
                    for (int nt = 0; nt < 2; nt++) {
                        const char* p = wb + s * 32 + nt * 10368;  // 8 rows * 1296B
                        Bh[nt][0] = *(const uint32_t*)(p);
                        Bh[nt][1] = *(const uint32_t*)(p + 16);
                        Bl[nt][0] = *(const uint32_t*)(p + W_VER);
                        Bl[nt][1] = *(const uint32_t*)(p + W_VER + 16);
                    }
#pragma unroll
                    for (int mt = 0; mt < 2; mt++)
#pragma unroll
                        for (int nt = 0; nt < 2; nt++) {
                            mma16816(D[mt][nt], Ah[mt], Bh[nt]);
                            mma16816(D[mt][nt], Ah[mt], Bl[nt]);
                            mma16816(D[mt][nt], Al[mt], Bh[nt]);
                        }
                }
            }
            __syncthreads();
            if (c < NCHUNK - 1) {        // STS chunk c+1
                char* zd = smem + OFF_Z + ((c + 1) & 1) * Z_BUF + sver * Z_VER
                           + sm * SZB + skh * 64;
#pragma unroll
                for (int i = 0; i < 4; i++) *(uint4*)(zd + i * 16) = v[i];
            }
            __syncthreads();
        }

        // ---- D fragments -> gates SMEM ----
#pragma unroll
        for (int mt = 0; mt < 2; mt++)
#pragma unroll
            for (int nt = 0; nt < 2; nt++) {
                int row = mtb + mt * 16 + g;
                int col = ntb + nt * 8 + tig * 2;
                *(float2*)(gates + row * GSTRIDE + col) =
                    make_float2(D[mt][nt][0], D[mt][nt][1]);
                *(float2*)(gates + (row + 8) * GSTRIDE + col) =
                    make_float2(D[mt][nt][2], D[mt][nt][3]);
            }
        __syncthreads();

        // ---- epilogue: thread owns (row sm, h-cols jb..jb+3) ----
        {
            const float* gr = gates + sm * GSTRIDE;
            const float4 gi  = *(const float4*)(gr + jb);
            const float4 gf  = *(const float4*)(gr + 16 + jb);
            const float4 gg4 = *(const float4*)(gr + 32 + jb);
            const float4 go  = *(const float4*)(gr + 48 + jb);
            float iv[4] = {gi.x + bi.x,  gi.y + bi.y,  gi.z + bi.z,  gi.w + bi.w};
            float fv[4] = {gf.x + bff.x, gf.y + bff.y, gf.z + bff.z, gf.w + bff.w};
            float gv[4] = {gg4.x + bgg.x, gg4.y + bgg.y, gg4.z + bgg.z, gg4.w + bgg.w};
            float ov[4] = {go.x + boo.x, go.y + boo.y, go.z + boo.z, go.w + boo.w};
            float hv[4];
#pragma unroll
            for (int u = 0; u < 4; u++) {
                float ig = fast_sigmoid(iv[u]);
                float fg = fast_sigmoid(fv[u]);
                float gg = fast_tanh(gv[u]);
                float og = fast_sigmoid(ov[u]);
                float cv = fg * c_st[u] + ig * gg;
                c_st[u] = cv;
                hv[u] = og * fast_tanh(cv);
                hsum[u] += hv[u];
            }
            const int pout = (t + 1) & 1;
            size_t off = (size_t)(m0 + sm) * HH + c0 + jb;
            uint32_t h0 = bf2(hv[0], hv[1]), h1 = bf2(hv[2], hv[3]);
            float r0 = hv[0] - __bfloat162float(__float2bfloat16(hv[0]));
            float r1 = hv[1] - __bfloat162float(__float2bfloat16(hv[1]));
            float r2 = hv[2] - __bfloat162float(__float2bfloat16(hv[2]));
            float r3 = hv[3] - __bfloat162float(__float2bfloat16(hv[3]));
            *(uint2*)(&g_hbf[pout][0][off]) = make_uint2(h0, h1);
            *(uint2*)(&g_hbf[pout][1][off]) = make_uint2(bf2(r0, r1), bf2(r2, r3));
        }
        __threadfence();
        __syncthreads();
        if (tid == 0) {
            unsigned a = atomicAdd(&g_mbar[mtile].count, 1u);
            if (a == NT_N - 1u) {
                atomicExch(&g_mbar[mtile].count, 0u);
                __threadfence();
                atomicAdd(&g_mbar[mtile].gen, 1u);
            }
        }
    }

    // ---- logits partials: combine the four j-quarters via SMEM ----
    {
        const int qidx = tid >> 6;        // 0..3
        const float inv_t = 1.f / (float)TT;
        float pl[CC];
#pragma unroll
        for (int cls = 0; cls < CC; cls++) {
            float s = 0.f;
#pragma unroll
            for (int u = 0; u < 4; u++)
                s += hsum[u] * __ldg(&W_lin[cls * HH + c0 + jb + u]);
            pl[cls] = s;
        }
        float* scr = gates;               // reuse as [64][4][10] scratch
#pragma unroll
        for (int cls = 0; cls < CC; cls++)
            scr[sm * 40 + qidx * 10 + cls] = pl[cls];
        __syncthreads();
        if (qidx == 0) {
#pragma unroll
            for (int cls = 0; cls < CC; cls++) {
                float s = scr[sm * 40 + cls] + scr[sm * 40 + 10 + cls]
                        + scr[sm * 40 + 20 + cls] + scr[sm * 40 + 30 + cls];
                g_partial[ntile][m0 + sm][cls] = s * inv_t;
            }
        }
    }

    // ---- final global barrier; CTA 0 reduces ----
    __threadfence();
    __syncthreads();
    if (tid == 0) {
        atomicAdd(&g_fbar.count, 1u);
        if (cta == 0) {
            while (*(volatile unsigned*)&g_fbar.count < (unsigned)GRID_SZ) { }
            __threadfence();
        }
    }
    __syncthreads();
    if (cta == 0) {
        for (int idx = tid; idx < BB * CC; idx += NTHR) {
            int b = idx / CC, cls = idx % CC;
            float s = __ldg(&b_lin[cls]);
#pragma unroll
            for (int n = 0; n < NT_N; n++) s += __ldcg(&g_partial[n][b][cls]);
            out[idx] = s;
        }
    }
}

extern "C" void kernel_launch(void* const* d_in, const int* in_sizes, int n_in,
                              void* d_out, int out_size) {
    const float* X     = (const float*)d_in[0];
    const float* W_ih  = (const float*)d_in[1];
    const float* W_hh  = (const float*)d_in[2];
    const float* b_ih  = (const float*)d_in[3];
    const float* b_hh  = (const float*)d_in[4];
    const float* W_lin = (const float*)d_in[5];
    const float* b_lin = (const float*)d_in[6];

    lstm_init<<<512, 256>>>(X);
    cudaFuncSetAttribute(lstm_mma,
                         cudaFuncAttributeMaxDynamicSharedMemorySize, SMEM_TOTAL);
    lstm_mma<<<GRID_SZ, NTHR, SMEM_TOTAL>>>(W_ih, W_hh, b_ih, b_hh,
                                            W_lin, b_lin, (float*)d_out);
}